// round 17
// baseline (speedup 1.0000x reference)
#include <cuda_runtime.h>
#include <cuda_fp16.h>
#include <cuda_fp8.h>
#include <math.h>

#define N_MAX 100000
#define E_MAX 1200000
#define F 64
#define PRE_B 256
#define ELLC 96
#define MAXPRE ((N_MAX + PRE_B - 1) / PRE_B)
#define HS_STR 72

// ---------------- scratch (static device globals) --------------------------
__device__ __align__(16) unsigned char g_xs8[(size_t)N_MAX * F]; // dis*(h@W2), fp8 e4m3
__device__ __half g_xp [(size_t)N_MAX * 8];          // dis_i*x_i, 5 dims padded to 8
__device__ __half g_z5 [(size_t)N_MAX * 8];          // gathered 5-dim sums, fp16
__device__ int    g_deg[N_MAX];                      // degree / fill cursor (zero at entry)
__device__ __align__(16) int g_ell[(size_t)N_MAX * ELLC];  // ELL src lists
__device__ float  g_dis[N_MAX];                      // rsqrt(deg+1)
__device__ float  g_emb[F];                          // column sums (zero at entry)
__device__ float  g_gfp[MAXPRE * 8];                 // per-block gfeat partials
__device__ __align__(16) __half g_w2t[F * HS_STR];   // W2 transposed fp16 [c][k]
__device__ int    g_ctr;                             // completion counter (zero at entry)

// ---------------- helpers ---------------------------------------------------
__device__ __forceinline__ int detect64(const unsigned int* p) {
    unsigned w = p[2 * (threadIdx.x & 31) + 1];
    return __all_sync(0xffffffffu, w == 0u);
}
__device__ __forceinline__ void hacc(__half2* ha, uint4 r) {
    __half2* h = (__half2*)&r;
#pragma unroll
    for (int i = 0; i < 4; i++) ha[i] = __hadd2(ha[i], h[i]);
}
__device__ __forceinline__ void hacc4(__half2* ha, uint4 a, uint4 b,
                                      uint4 c, uint4 d) {
    __half2* pa = (__half2*)&a;
    __half2* pb = (__half2*)&b;
    __half2* pc = (__half2*)&c;
    __half2* pd = (__half2*)&d;
#pragma unroll
    for (int i = 0; i < 4; i++) {
        __half2 t = __hadd2(__hadd2(pa[i], pb[i]), __hadd2(pc[i], pd[i]));
        ha[i] = __hadd2(ha[i], t);
    }
}
__device__ __forceinline__ void hflush(float* s, const __half2* ha) {
#pragma unroll
    for (int i = 0; i < 4; i++) {
        float2 f = __half22float2(ha[i]);
        s[2 * i]     += f.x;
        s[2 * i + 1] += f.y;
    }
}
__device__ __forceinline__ void hacc_f8(__half2* ha, uint2 r) {
    __nv_fp8x2_storage_t* p = (__nv_fp8x2_storage_t*)&r;
#pragma unroll
    for (int i = 0; i < 4; i++) {
        __half2_raw hr = __nv_cvt_fp8x2_to_halfraw2(p[i], __NV_E4M3);
        ha[i] = __hadd2(ha[i], *(__half2*)&hr);
    }
}
// 64-dim gather over fp8 xs, ELL edges + self
__device__ __forceinline__ void gather_row8(float* s, int node, int sub) {
    const uint2* xsv = (const uint2*)g_xs8;
    int beg = node * ELLC;
    int end = beg + min(g_deg[node], ELLC);
    __half2 ha[4];
    {
        __half2 z = __float2half2_rn(0.0f);
#pragma unroll
        for (int i = 0; i < 4; i++) ha[i] = z;
    }
    hacc_f8(ha, xsv[(size_t)node * 8 + sub]);        // self (xs prescaled)
    int e = beg;
#pragma unroll 1
    for (; e + 4 <= end; e += 4) {
        int4 si = *(const int4*)&g_ell[e];
        uint2 r0 = xsv[(size_t)si.x * 8 + sub];
        uint2 r1 = xsv[(size_t)si.y * 8 + sub];
        uint2 r2 = xsv[(size_t)si.z * 8 + sub];
        uint2 r3 = xsv[(size_t)si.w * 8 + sub];
        hacc_f8(ha, r0); hacc_f8(ha, r1);
        hacc_f8(ha, r2); hacc_f8(ha, r3);
    }
#pragma unroll 1
    for (; e < end; e++)
        hacc_f8(ha, xsv[(size_t)g_ell[e] * 8 + sub]);
    hflush(s, ha);
}
// 5-dim gather over ELL range [b0, e0)
__device__ __forceinline__ void gather_range5(float* s, int b0, int e0,
                                              int node, int withSelf) {
    const uint4* xp = (const uint4*)g_xp;
    __half2 ha[4];
    if (withSelf) {
        uint4 sv = xp[node];
#pragma unroll
        for (int i = 0; i < 4; i++) ha[i] = ((__half2*)&sv)[i];
    } else {
        __half2 z = __float2half2_rn(0.0f);
#pragma unroll
        for (int i = 0; i < 4; i++) ha[i] = z;
    }
    int e = b0;
    int pro = (4 - (e & 3)) & 3;
    pro = min(pro, e0 - e);
#pragma unroll 1
    for (int k = 0; k < pro; k++, e++)
        hacc(ha, xp[g_ell[e]]);
#pragma unroll 1
    for (; e + 4 <= e0; e += 4) {
        int4 si = *(const int4*)&g_ell[e];
        hacc4(ha, xp[si.x], xp[si.y], xp[si.z], xp[si.w]);
    }
#pragma unroll 1
    for (; e < e0; e++)
        hacc(ha, xp[g_ell[e]]);
    hflush(s, ha);
}

// ---------------- kernel 1: gfeat partials | direct ELL fill -----------------
__global__ void fill_kernel(const float* __restrict__ x,
                            const void* __restrict__ eidx,
                            int n, int E, int nbG) {
    int bid = blockIdx.x;
    int tid = threadIdx.x;

    if (bid < nbG) {
        __shared__ float sw[8][6];
        if (bid == 0 && tid < F) g_emb[tid] = 0.0f;
        int i = bid * PRE_B + tid;
        float s2 = 0, s3 = 0, s4 = 0, sm = 0, sl = 0, su = 0;
        if (i < n) {
            const float* r = &x[(size_t)i * 5];
            float x0 = r[0], x1 = r[1];
            s2 = r[2]; s3 = r[3]; s4 = r[4];
            float m = (s2 == 1.0f) ? 1.0f : 0.0f;
            sm = m; sl = x0 * m; su = x1 * m;
        }
#pragma unroll
        for (int o = 16; o > 0; o >>= 1) {
            s2 += __shfl_down_sync(0xffffffffu, s2, o);
            s3 += __shfl_down_sync(0xffffffffu, s3, o);
            s4 += __shfl_down_sync(0xffffffffu, s4, o);
            sm += __shfl_down_sync(0xffffffffu, sm, o);
            sl += __shfl_down_sync(0xffffffffu, sl, o);
            su += __shfl_down_sync(0xffffffffu, su, o);
        }
        int w = tid >> 5;
        if ((tid & 31) == 0) {
            sw[w][0] = s2; sw[w][1] = s3; sw[w][2] = s4;
            sw[w][3] = sm; sw[w][4] = sl; sw[w][5] = su;
        }
        __syncthreads();
        if (tid < 6) {
            float acc = 0.0f;
#pragma unroll
            for (int q = 0; q < 8; q++) acc += sw[q][tid];
            g_gfp[bid * 8 + tid] = acc;
        }
    } else {
        int is64 = detect64((const unsigned int*)eidx);
        int e = (bid - nbG) * PRE_B + tid;
        if (e >= E) return;
        int s, d;
        if (is64) {
            const long long* p = (const long long*)eidx;
            s = (int)p[e];
            d = (int)p[(size_t)E + e];
        } else {
            const int* p = (const int*)eidx;
            s = p[e];
            d = p[E + e];
        }
        s = min(max(s, 0), n - 1);
        d = min(max(d, 0), n - 1);
        int idx = atomicAdd(&g_deg[d], 1);
        if (idx < ELLC) g_ell[d * ELLC + idx] = s;   // overflow prob ~0
    }
}

// ---------------- kernel 2: dis + xp; block 0 also precomputes w2t ----------
__global__ void disxp_kernel(const float* __restrict__ x,
                             const float* __restrict__ W2, int n) {
    int tid = threadIdx.x;
    if (blockIdx.x == 0) {
#pragma unroll
        for (int q = 0; q < 16; q++) {
            int idx = tid + q * 256;          // idx < 4096 = F*F
            int k = idx >> 6, c = idx & 63;
            g_w2t[c * HS_STR + k] = __float2half_rn(W2[idx]);
        }
    }
    int node = blockIdx.x * blockDim.x + tid;
    if (node >= n) return;
    float dn = rsqrtf((float)g_deg[node] + 1.0f);
    g_dis[node] = dn;
    const float* r = &x[(size_t)node * 5];
    __half2 oh[4];
    oh[0] = __floats2half2_rn(dn * r[0], dn * r[1]);
    oh[1] = __floats2half2_rn(dn * r[2], dn * r[3]);
    oh[2] = __floats2half2_rn(dn * r[4], 0.0f);
    oh[3] = __floats2half2_rn(0.0f, 0.0f);
    ((uint4*)g_xp)[node] = *(uint4*)oh;
}

// ---------------- layer-1 gather in 5-dim space, 2 lanes/node ---------------
__global__ void gatherz_kernel(int n) {
    int tid  = threadIdx.x;
    int nl   = tid >> 1;
    int cg   = tid & 1;
    int node = blockIdx.x * 128 + nl;
    float s[8] = {0, 0, 0, 0, 0, 0, 0, 0};
    float dn = 0.0f;
    if (node < n) {
        dn = g_dis[node];
        int cnt = min(g_deg[node], ELLC);
        int beg = node * ELLC;
        int half = (cnt + 1) >> 1;
        int b0 = cg ? beg + half : beg;
        int e0 = cg ? beg + cnt : beg + half;
        gather_range5(s, b0, e0, node, cg == 0);
    }
#pragma unroll
    for (int j = 0; j < 5; j++)
        s[j] += __shfl_xor_sync(0xffffffffu, s[j], 1);
    if (node < n && cg == 0) {
        __half2 oh[4];
        oh[0] = __floats2half2_rn(dn * s[0], dn * s[1]);
        oh[1] = __floats2half2_rn(dn * s[2], dn * s[3]);
        oh[2] = __floats2half2_rn(dn * s[4], 0.0f);
        oh[3] = __floats2half2_rn(0.0f, 0.0f);
        ((uint4*)g_z5)[node] = *(uint4*)oh;
    }
}

// ---------------- xw2: h = relu(z5@W1 + b1); xs8 = fp8(dis*(h@W2)) -----------
__global__ void xw2_kernel(const float* __restrict__ W1,
                           const float* __restrict__ b1, int n) {
    __shared__ __half hs [128 * HS_STR];   // reused as fp8 staging after MMA
    __shared__ __half w2t[F * HS_STR];
    __shared__ float  W1s[5 * F];
    __shared__ float  b1s[F];
    int tid  = threadIdx.x;
    int base = blockIdx.x * 128;

    // vectorized copy of precomputed w2t (no transpose, no conflicts)
    for (int i = tid; i < (F * HS_STR) / 8; i += 256)
        ((uint4*)w2t)[i] = ((const uint4*)g_w2t)[i];
    for (int idx = tid; idx < 5 * F; idx += 256) W1s[idx] = W1[idx];
    if (tid < F) b1s[tid] = b1[tid];
    __syncthreads();

    // h compute: 2 threads/node, 32 cols each
    {
        int nl   = tid >> 1;
        int cg   = tid & 1;
        int node = base + nl;
        float z[5] = {0, 0, 0, 0, 0};
        if (node < n) {
            uint4 zv = ((const uint4*)g_z5)[node];
            __half2* h = (__half2*)&zv;
            float2 f0 = __half22float2(h[0]);
            float2 f1 = __half22float2(h[1]);
            float2 f2 = __half22float2(h[2]);
            z[0] = f0.x; z[1] = f0.y; z[2] = f1.x; z[3] = f1.y; z[4] = f2.x;
        }
        float a[32];
#pragma unroll
        for (int c = 0; c < 32; c++) a[c] = b1s[cg * 32 + c];
#pragma unroll
        for (int k = 0; k < 5; k++) {
            float zk = z[k];
#pragma unroll
            for (int c = 0; c < 32; c++)
                a[c] += zk * W1s[k * F + cg * 32 + c];
        }
        __half2 hp[16];
#pragma unroll
        for (int j = 0; j < 16; j++)
            hp[j] = __floats2half2_rn(fmaxf(a[2 * j], 0.f),
                                      fmaxf(a[2 * j + 1], 0.f));
        uint4* dst = (uint4*)&hs[nl * HS_STR + cg * 32];
#pragma unroll
        for (int q = 0; q < 4; q++) dst[q] = ((uint4*)hp)[q];
    }
    __syncthreads();

    // MMA phase: 8 warps × 16 rows
    int w    = tid >> 5;
    int lane = tid & 31;
    int g    = lane >> 2;
    int t    = lane & 3;
    int r0   = w * 16 + g;

    float d[8][4];
#pragma unroll
    for (int ct = 0; ct < 8; ct++)
#pragma unroll
        for (int j = 0; j < 4; j++) d[ct][j] = 0.0f;

#pragma unroll
    for (int kc = 0; kc < 4; kc++) {
        int kb = kc * 16 + 2 * t;
        unsigned a0 = *(const unsigned*)&hs[(size_t)r0       * HS_STR + kb];
        unsigned a1 = *(const unsigned*)&hs[(size_t)(r0 + 8) * HS_STR + kb];
        unsigned a2 = *(const unsigned*)&hs[(size_t)r0       * HS_STR + kb + 8];
        unsigned a3 = *(const unsigned*)&hs[(size_t)(r0 + 8) * HS_STR + kb + 8];
#pragma unroll
        for (int ct = 0; ct < 8; ct++) {
            int c = ct * 8 + g;
            unsigned b0 = *(const unsigned*)&w2t[c * HS_STR + kb];
            unsigned bb1 = *(const unsigned*)&w2t[c * HS_STR + kb + 8];
            asm volatile(
                "mma.sync.aligned.m16n8k16.row.col.f32.f16.f16.f32 "
                "{%0,%1,%2,%3},{%4,%5,%6,%7},{%8,%9},{%0,%1,%2,%3};\n"
                : "+f"(d[ct][0]), "+f"(d[ct][1]), "+f"(d[ct][2]), "+f"(d[ct][3])
                : "r"(a0), "r"(a1), "r"(a2), "r"(a3), "r"(b0), "r"(bb1));
        }
    }
    __syncthreads();            // all warps done reading hs

    // stage fp8 output in smem (reuse hs), then coalesced global store
    unsigned char* o8 = (unsigned char*)hs;
    {
        int node0 = base + r0;
        int node1 = node0 + 8;
        float dn0 = (node0 < n) ? g_dis[node0] : 0.0f;
        float dn1 = (node1 < n) ? g_dis[node1] : 0.0f;
#pragma unroll
        for (int ct = 0; ct < 8; ct++) {
            int c = ct * 8 + 2 * t;
            __nv_fp8x2_storage_t v0 = __nv_cvt_float2_to_fp8x2(
                make_float2(d[ct][0] * dn0, d[ct][1] * dn0),
                __NV_SATFINITE, __NV_E4M3);
            __nv_fp8x2_storage_t v1 = __nv_cvt_float2_to_fp8x2(
                make_float2(d[ct][2] * dn1, d[ct][3] * dn1),
                __NV_SATFINITE, __NV_E4M3);
            *(unsigned short*)&o8[r0 * 64 + c]        = *(unsigned short*)&v0;
            *(unsigned short*)&o8[(r0 + 8) * 64 + c]  = *(unsigned short*)&v1;
        }
    }
    __syncthreads();
    for (int i = tid; i < 128 * 4; i += 256) {
        int nl = i >> 2;
        int node = base + nl;
        if (node < n)
            ((uint4*)&g_xs8[(size_t)node * F])[i & 3] = ((const uint4*)o8)[i];
    }
}

// ---------------- gather2 (fp8, 8 lanes/node) + pool + final MLP -------------
__global__ void gather2_kernel(const float* __restrict__ b,
                               const float* __restrict__ Wp1,
                               const float* __restrict__ bp1,
                               const float* __restrict__ Wp2,
                               const float* __restrict__ bp2,
                               const int* __restrict__ Tp,
                               const int* __restrict__ Tmp,
                               float* __restrict__ out, int n, int nbG) {
    __shared__ float colsum[F];
    __shared__ int   islast;
    int tid  = threadIdx.x;
    int sub  = tid & 7;
    int node = blockIdx.x * 32 + (tid >> 3);
    bool valid = node < n;

    if (tid < F) colsum[tid] = 0.0f;
    __syncthreads();

    float s[8] = {0, 0, 0, 0, 0, 0, 0, 0};
    float dn = 0.0f;
    if (valid) {
        dn = g_dis[node];
        gather_row8(s, node, sub);
        if (sub == 0) g_deg[node] = 0;     // reset for next call
    }

    float4 b0 = ((const float4*)b)[sub * 2];
    float4 b1 = ((const float4*)b)[sub * 2 + 1];
    float bv[8] = {b0.x, b0.y, b0.z, b0.w, b1.x, b1.y, b1.z, b1.w};

#pragma unroll
    for (int j = 0; j < 8; j++) {
        float v = valid ? fmaxf(dn * s[j] + bv[j], 0.0f) : 0.0f;
        v += __shfl_down_sync(0xffffffffu, v, 16);
        v += __shfl_down_sync(0xffffffffu, v, 8);
        if ((tid & 31) < 8) atomicAdd(&colsum[sub * 8 + j], v);
    }
    __syncthreads();
    if (tid < F) atomicAdd(&g_emb[tid], colsum[tid]);

    __threadfence();
    if (tid == 0) {
        int old = atomicAdd(&g_ctr, 1);
        islast = (old == (int)gridDim.x - 1);
    }
    __syncthreads();
    if (!islast) return;
    __threadfence();

    __shared__ float e[71];
    __shared__ float hid[32];
    __shared__ float gf6[6];
    if (tid < 64) e[tid] = g_emb[tid] / (float)n;

    int w = tid >> 5, lane = tid & 31;
    if (w < 6) {
        float sg = 0.0f;
        for (int bb = lane; bb < nbG; bb += 32) sg += g_gfp[bb * 8 + w];
#pragma unroll
        for (int o = 16; o > 0; o >>= 1)
            sg += __shfl_down_sync(0xffffffffu, sg, o);
        if (lane == 0) gf6[w] = sg;
    }
    __syncthreads();
    if (tid == 64) {
        float nAND = gf6[1], nOR = gf6[2];
        e[64] = gf6[0];
        e[65] = nAND;
        e[66] = nOR;
        e[67] = nAND + nOR;
        float msum = gf6[3];
        float safe = fmaxf(msum, 1.0f);
        e[68] = (msum > 0.0f) ? gf6[4] / safe : 0.0f;
        e[69] = (msum > 0.0f) ? gf6[5] / safe : 0.0f;
        e[70] = (float)(*Tp) / (float)(*Tmp);
    }
    __syncthreads();
    if (tid < 32) {
        float a = bp1[tid];
        for (int k = 0; k < 71; k++) a += e[k] * Wp1[k * 32 + tid];
        hid[tid] = fmaxf(a, 0.0f);
    }
    __syncthreads();
    if (tid < 2) {
        float r = bp2[tid];
#pragma unroll
        for (int j = 0; j < 32; j++) r += hid[j] * Wp2[j * 2 + tid];
        out[tid] = 2.0f + 4.0f / (1.0f + expf(-r));
    }
    if (tid < F) g_emb[tid] = 0.0f;
    if (tid == 0) g_ctr = 0;
}

// ---------------- launch ------------------------------------------------------
extern "C" void kernel_launch(void* const* d_in, const int* in_sizes, int n_in,
                              void* d_out, int out_size) {
    const float* x   = (const float*)d_in[0];
    const void*  ei  = d_in[1];
    const float* W1  = (const float*)d_in[2];
    const float* b1  = (const float*)d_in[3];
    const float* W2  = (const float*)d_in[4];
    const float* b2  = (const float*)d_in[5];
    const float* Wp1 = (const float*)d_in[6];
    const float* bp1 = (const float*)d_in[7];
    const float* Wp2 = (const float*)d_in[8];
    const float* bp2 = (const float*)d_in[9];
    const int*   Tp  = (const int*)d_in[10];
    const int*   Tmp = (const int*)d_in[11];
    float* out = (float*)d_out;

    int n = in_sizes[0] / 5;
    int E = in_sizes[1] / 2;
    int nbG = (n + PRE_B - 1) / PRE_B;
    int nbF = (E + PRE_B - 1) / PRE_B;

    fill_kernel<<<nbG + nbF, PRE_B>>>(x, ei, n, E, nbG);
    disxp_kernel<<<(n + 255) / 256, 256>>>(x, W2, n);
    gatherz_kernel<<<(n + 127) / 128, 256>>>(n);
    xw2_kernel<<<(n + 127) / 128, 256>>>(W1, b1, n);
    gather2_kernel<<<(n + 31) / 32, 256>>>(b2, Wp1, bp1, Wp2, bp2,
                                           Tp, Tmp, out, n, nbG);
}